// round 1
// baseline (speedup 1.0000x reference)
#include <cuda_runtime.h>
#include <mma.h>
#include <math.h>

using namespace nvcuda;

// Problem constants
// B=4, T=2048, E=1024, H=16, D=64
#define TB 4
#define TT 2048
#define TE 1024
#define TH 16
#define TD 64

// Scratch (device globals: allowed by harness rules)
static __device__ float g_qkv[8192 * 3072]; // [B*T, 3E]
static __device__ float g_y[8192 * 1024];   // [B*T, E] attention output

// ---------------------------------------------------------------------------
// Split fp32 into tf32 hi + lo  (3xTF32 trick for near-fp32 accuracy)
// ---------------------------------------------------------------------------
__device__ __forceinline__ void split_tf32(float x, float& hi, float& lo) {
    hi = __uint_as_float(__float_as_uint(x) & 0xFFFFE000u);
    lo = x - hi;
}

// ---------------------------------------------------------------------------
// GEMM: C[M,N] = A[M,K] @ B[K,N] + bias[N]    (3xTF32, wmma m16n16k8)
// Block tile: 64x128, BK=16, 256 threads (8 warps, warp tile 32x32)
// ---------------------------------------------------------------------------
__global__ __launch_bounds__(256) void gemm3x_kernel(
    const float* __restrict__ A, const float* __restrict__ Bw,
    const float* __restrict__ bias, float* __restrict__ C,
    int M, int N, int K)
{
    __shared__ float buf[8448]; // max(As+Bs (6784), Ctile 64*132 (8448))
    float* As_hi = buf;          // [64][20]
    float* As_lo = buf + 1280;
    float* Bs_hi = buf + 2560;   // [16][132]
    float* Bs_lo = buf + 4672;

    const int tid = threadIdx.x;
    const int wid = tid >> 5;
    const int warp_row = wid >> 2;   // 0..1  (32 rows each)
    const int warp_col = wid & 3;    // 0..3  (32 cols each)
    const int bm = blockIdx.y * 64;
    const int bn = blockIdx.x * 128;

    wmma::fragment<wmma::accumulator, 16, 16, 8, float> acc[2][2];
#pragma unroll
    for (int i = 0; i < 2; i++)
#pragma unroll
        for (int j = 0; j < 2; j++) wmma::fill_fragment(acc[i][j], 0.0f);

    const int a_row = tid >> 2;          // 0..63
    const int a_col = (tid & 3) * 4;     // 0,4,8,12
    const int b_row = tid >> 4;          // 0..15
    const int b_col = (tid & 15) * 4;    // 0..60

    for (int k0 = 0; k0 < K; k0 += 16) {
        __syncthreads();
        // Load A tile 64x16
        {
            float4 av = *(const float4*)(A + (size_t)(bm + a_row) * K + (k0 + a_col));
            float ax[4] = {av.x, av.y, av.z, av.w};
#pragma unroll
            for (int i = 0; i < 4; i++) {
                float hi, lo; split_tf32(ax[i], hi, lo);
                As_hi[a_row * 20 + a_col + i] = hi;
                As_lo[a_row * 20 + a_col + i] = lo;
            }
        }
        // Load B tile 16x128 (two float4 per thread)
#pragma unroll
        for (int half = 0; half < 2; half++) {
            int col = b_col + half * 64;
            float4 bv = *(const float4*)(Bw + (size_t)(k0 + b_row) * N + bn + col);
            float bx[4] = {bv.x, bv.y, bv.z, bv.w};
#pragma unroll
            for (int i = 0; i < 4; i++) {
                float hi, lo; split_tf32(bx[i], hi, lo);
                Bs_hi[b_row * 132 + col + i] = hi;
                Bs_lo[b_row * 132 + col + i] = lo;
            }
        }
        __syncthreads();

#pragma unroll
        for (int ks = 0; ks < 16; ks += 8) {
            wmma::fragment<wmma::matrix_a, 16, 16, 8, wmma::precision::tf32, wmma::row_major> a_hi[2], a_lo[2];
            wmma::fragment<wmma::matrix_b, 16, 16, 8, wmma::precision::tf32, wmma::row_major> b_hi[2], b_lo[2];
#pragma unroll
            for (int mm = 0; mm < 2; mm++) {
                int row = warp_row * 32 + mm * 16;
                wmma::load_matrix_sync(a_hi[mm], As_hi + row * 20 + ks, 20);
                wmma::load_matrix_sync(a_lo[mm], As_lo + row * 20 + ks, 20);
            }
#pragma unroll
            for (int nn = 0; nn < 2; nn++) {
                int col = warp_col * 32 + nn * 16;
                wmma::load_matrix_sync(b_hi[nn], Bs_hi + ks * 132 + col, 132);
                wmma::load_matrix_sync(b_lo[nn], Bs_lo + ks * 132 + col, 132);
            }
#pragma unroll
            for (int mm = 0; mm < 2; mm++)
#pragma unroll
                for (int nn = 0; nn < 2; nn++) {
                    wmma::mma_sync(acc[mm][nn], a_hi[mm], b_hi[nn], acc[mm][nn]);
                    wmma::mma_sync(acc[mm][nn], a_hi[mm], b_lo[nn], acc[mm][nn]);
                    wmma::mma_sync(acc[mm][nn], a_lo[mm], b_hi[nn], acc[mm][nn]);
                }
        }
    }

    // Epilogue: stage to smem, add bias, write out
    __syncthreads();
#pragma unroll
    for (int mm = 0; mm < 2; mm++)
#pragma unroll
        for (int nn = 0; nn < 2; nn++) {
            wmma::store_matrix_sync(buf + (warp_row * 32 + mm * 16) * 132 + warp_col * 32 + nn * 16,
                                    acc[mm][nn], 132, wmma::mem_row_major);
        }
    __syncthreads();
    for (int i = tid; i < 64 * 128; i += 256) {
        int r = i >> 7, c = i & 127;
        C[(size_t)(bm + r) * N + bn + c] = buf[r * 132 + c] + bias[bn + c];
    }
}

// ---------------------------------------------------------------------------
// Flash attention (causal). One block = one (b,h) x one 64-query tile.
// 256 threads, 8 warps. wmma tf32 for QK^T and PV; fp32 online softmax.
// ---------------------------------------------------------------------------
__global__ __launch_bounds__(256) void attn_kernel()
{
    extern __shared__ float sm[];
    float* Qs  = sm;            // [64][68] (pre-scaled by 1/8)
    float* KVs = sm + 4352;     // [64][68] K tile then V tile
    float* Ss  = sm + 8704;     // [64][68] scores / probabilities
    float* Os  = sm + 13056;    // [64][68] output accumulator
    float* row_m = sm + 17408;  // [64]
    float* row_l = row_m + 64;  // [64]

    const int tid = threadIdx.x;
    const int wid = tid >> 5;
    const int lane = tid & 31;
    const int qblock = blockIdx.x;        // 0..31
    const int bh = blockIdx.y;            // 0..63
    const int b = bh >> 4, h = bh & 15;

    const int r = tid >> 2;               // 0..63 (row for tile loads)
    const int cseg = (tid & 3) * 16;      // 16-col segment

    // Load Q tile (scaled by 1/sqrt(D)=0.125)
    {
        const float* src = g_qkv + ((size_t)(b * TT + qblock * 64 + r)) * 3072 + h * 64 + cseg;
#pragma unroll
        for (int i = 0; i < 16; i += 4) {
            float4 v = *(const float4*)(src + i);
            Qs[r * 68 + cseg + i + 0] = v.x * 0.125f;
            Qs[r * 68 + cseg + i + 1] = v.y * 0.125f;
            Qs[r * 68 + cseg + i + 2] = v.z * 0.125f;
            Qs[r * 68 + cseg + i + 3] = v.w * 0.125f;
        }
    }
    for (int i = tid; i < 64 * 68; i += 256) Os[i] = 0.0f;
    if (tid < 64) { row_m[tid] = -1e30f; row_l[tid] = 0.0f; }
    __syncthreads();

    const int warp_m = wid >> 1;   // 0..3 -> 16 query rows
    const int warp_n = wid & 1;    // 0..1 -> 32 key cols

    for (int j = 0; j <= qblock; j++) {
        // Load K tile into KVs
        {
            const float* src = g_qkv + ((size_t)(b * TT + j * 64 + r)) * 3072 + 1024 + h * 64 + cseg;
#pragma unroll
            for (int i = 0; i < 16; i += 4) {
                float4 v = *(const float4*)(src + i);
                KVs[r * 68 + cseg + i + 0] = v.x;
                KVs[r * 68 + cseg + i + 1] = v.y;
                KVs[r * 68 + cseg + i + 2] = v.z;
                KVs[r * 68 + cseg + i + 3] = v.w;
            }
        }
        __syncthreads();

        // S = Q @ K^T   (tf32)
        {
            wmma::fragment<wmma::accumulator, 16, 16, 8, float> s_acc[2];
            wmma::fill_fragment(s_acc[0], 0.0f);
            wmma::fill_fragment(s_acc[1], 0.0f);
#pragma unroll
            for (int kk = 0; kk < 64; kk += 8) {
                wmma::fragment<wmma::matrix_a, 16, 16, 8, wmma::precision::tf32, wmma::row_major> a_f;
                wmma::load_matrix_sync(a_f, Qs + (warp_m * 16) * 68 + kk, 68);
#pragma unroll
                for (int nn = 0; nn < 2; nn++) {
                    wmma::fragment<wmma::matrix_b, 16, 16, 8, wmma::precision::tf32, wmma::col_major> b_f;
                    wmma::load_matrix_sync(b_f, KVs + (warp_n * 32 + nn * 16) * 68 + kk, 68);
                    wmma::mma_sync(s_acc[nn], a_f, b_f, s_acc[nn]);
                }
            }
#pragma unroll
            for (int nn = 0; nn < 2; nn++)
                wmma::store_matrix_sync(Ss + (warp_m * 16) * 68 + warp_n * 32 + nn * 16,
                                        s_acc[nn], 68, wmma::mem_row_major);
        }
        __syncthreads();

        // Load V tile into KVs (K no longer needed)
        {
            const float* src = g_qkv + ((size_t)(b * TT + j * 64 + r)) * 3072 + 2048 + h * 64 + cseg;
#pragma unroll
            for (int i = 0; i < 16; i += 4) {
                float4 v = *(const float4*)(src + i);
                KVs[r * 68 + cseg + i + 0] = v.x;
                KVs[r * 68 + cseg + i + 1] = v.y;
                KVs[r * 68 + cseg + i + 2] = v.z;
                KVs[r * 68 + cseg + i + 3] = v.w;
            }
        }

        // Online softmax. Warp wid handles rows wid*8 .. wid*8+7.
        const bool diag = (j == qblock);
#pragma unroll
        for (int rr = 0; rr < 8; rr++) {
            int row = wid * 8 + rr;
            float s0 = Ss[row * 68 + lane];
            float s1 = Ss[row * 68 + 32 + lane];
            if (diag) {
                if (lane > row) s0 = -1e30f;
                if (32 + lane > row) s1 = -1e30f;
            }
            float mt = fmaxf(s0, s1);
#pragma unroll
            for (int off = 16; off; off >>= 1)
                mt = fmaxf(mt, __shfl_xor_sync(0xFFFFFFFFu, mt, off));
            float mo = row_m[row];
            float mn = fmaxf(mo, mt);
            float alpha = __expf(mo - mn);
            float p0 = __expf(s0 - mn);
            float p1 = __expf(s1 - mn);
            Ss[row * 68 + lane] = p0;
            Ss[row * 68 + 32 + lane] = p1;
            float psum = p0 + p1;
#pragma unroll
            for (int off = 16; off; off >>= 1)
                psum += __shfl_xor_sync(0xFFFFFFFFu, psum, off);
            if (lane == 0) {
                row_m[row] = mn;
                row_l[row] = alpha * row_l[row] + psum;
            }
            Os[row * 68 + lane] *= alpha;
            Os[row * 68 + 32 + lane] *= alpha;
        }
        __syncthreads();

        // O += P @ V  (tf32); accumulator lives in Os (just rescaled)
        {
            wmma::fragment<wmma::accumulator, 16, 16, 8, float> o_acc[2];
#pragma unroll
            for (int nn = 0; nn < 2; nn++)
                wmma::load_matrix_sync(o_acc[nn],
                                       Os + (warp_m * 16) * 68 + warp_n * 32 + nn * 16,
                                       68, wmma::mem_row_major);
#pragma unroll
            for (int kk = 0; kk < 64; kk += 8) {
                wmma::fragment<wmma::matrix_a, 16, 16, 8, wmma::precision::tf32, wmma::row_major> a_f;
                wmma::load_matrix_sync(a_f, Ss + (warp_m * 16) * 68 + kk, 68);
#pragma unroll
                for (int nn = 0; nn < 2; nn++) {
                    wmma::fragment<wmma::matrix_b, 16, 16, 8, wmma::precision::tf32, wmma::row_major> b_f;
                    wmma::load_matrix_sync(b_f, KVs + kk * 68 + warp_n * 32 + nn * 16, 68);
                    wmma::mma_sync(o_acc[nn], a_f, b_f, o_acc[nn]);
                }
            }
#pragma unroll
            for (int nn = 0; nn < 2; nn++)
                wmma::store_matrix_sync(Os + (warp_m * 16) * 68 + warp_n * 32 + nn * 16,
                                        o_acc[nn], 68, wmma::mem_row_major);
        }
        __syncthreads();
    }

    // Normalize and write y[b, t, h*64 + d]
#pragma unroll
    for (int rr = 0; rr < 8; rr++) {
        int row = wid * 8 + rr;
        float inv = 1.0f / row_l[row];
        int t = qblock * 64 + row;
        float* dst = g_y + ((size_t)(b * TT + t)) * 1024 + h * 64;
        dst[lane] = Os[row * 68 + lane] * inv;
        dst[32 + lane] = Os[row * 68 + 32 + lane] * inv;
    }
}

// ---------------------------------------------------------------------------
// kernel_launch
// Inputs: 0=x [4,2048,1024] f32, 1=mask (ignored; causal structure known),
//         2=W_attn [1024,3072], 3=b_attn [3072], 4=W_proj [1024,1024],
//         5=b_proj [1024].  Output: [4,2048,1024] f32.
// ---------------------------------------------------------------------------
extern "C" void kernel_launch(void* const* d_in, const int* in_sizes, int n_in,
                              void* d_out, int out_size)
{
    const float* x  = (const float*)d_in[0];
    const float* Wa = (const float*)d_in[2];
    const float* ba = (const float*)d_in[3];
    const float* Wp = (const float*)d_in[4];
    const float* bp = (const float*)d_in[5];
    float* out = (float*)d_out;

    void* qkv_ptr = nullptr;
    void* y_ptr = nullptr;
    cudaGetSymbolAddress(&qkv_ptr, g_qkv);
    cudaGetSymbolAddress(&y_ptr, g_y);

    cudaFuncSetAttribute((const void*)attn_kernel,
                         cudaFuncAttributeMaxDynamicSharedMemorySize, 70144);

    // qkv = x @ W_attn + b_attn
    gemm3x_kernel<<<dim3(3072 / 128, 8192 / 64), 256>>>(
        x, Wa, ba, (float*)qkv_ptr, 8192, 3072, 1024);

    // y = causal multi-head attention(qkv)
    attn_kernel<<<dim3(TT / 64, TB * TH), 256, 70144>>>();

    // out = y @ W_proj + b_proj
    gemm3x_kernel<<<dim3(1024 / 128, 8192 / 64), 256>>>(
        (float*)y_ptr, Wp, bp, out, 8192, 1024, 1024);
}

// round 3
// speedup vs baseline: 2.2635x; 2.2635x over previous
#include <cuda_runtime.h>
#include <cuda_bf16.h>
#include <mma.h>
#include <math.h>

using namespace nvcuda;

// B=4, T=2048, E=1024, H=16, D=64
#define TB 4
#define TT 2048
#define TE 1024
#define TH 16
#define TD 64

// Scratch (device globals: allowed)
static __device__ __nv_bfloat16 g_qkv_hi[8192 * 3072];
static __device__ __nv_bfloat16 g_qkv_lo[8192 * 3072];
static __device__ float g_y[8192 * 1024];

// Split fp32 -> bf16 hi + bf16 lo (residual). hi*hi+hi*lo+lo*hi in fp32 acc
// gives ~2^-16 relative error per element.
__device__ __forceinline__ void split_bf16(float x, __nv_bfloat16& hi, __nv_bfloat16& lo) {
    hi = __float2bfloat16(x);
    lo = __float2bfloat16(x - __bfloat162float(hi));
}

__device__ __forceinline__ void sts8(__nv_bfloat16* dhi, __nv_bfloat16* dlo,
                                     float4 v0, float4 v1) {
    float f[8] = {v0.x, v0.y, v0.z, v0.w, v1.x, v1.y, v1.z, v1.w};
    __nv_bfloat16 th[8], tl[8];
#pragma unroll
    for (int j = 0; j < 8; j++) split_bf16(f[j], th[j], tl[j]);
    *(uint4*)dhi = *(uint4*)th;
    *(uint4*)dlo = *(uint4*)tl;
}

// ---------------------------------------------------------------------------
// GEMM: C[M,N] = A[M,K](fp32) @ B[K,N](fp32) + bias
// bf16 3-term split, wmma m16n16k16. Tile 128x128, BK=16, 256 thr (8 warps,
// warp tile 32x64). Double-buffered smem, register prefetch, 1 sync/iter.
// Output: fp32 (Cf) or bf16 hi/lo pair (Chi/Clo) if Chi != nullptr.
// ---------------------------------------------------------------------------
__global__ __launch_bounds__(256, 2) void gemm_bf16_kernel(
    const float* __restrict__ A, const float* __restrict__ Bw,
    const float* __restrict__ bias,
    float* __restrict__ Cf,
    __nv_bfloat16* __restrict__ Chi, __nv_bfloat16* __restrict__ Clo,
    int M, int N, int K)
{
    __shared__ __align__(16) char smem_raw[41984];
    __nv_bfloat16* Ah = (__nv_bfloat16*)smem_raw;             // [2][128*24]
    __nv_bfloat16* Al = (__nv_bfloat16*)(smem_raw + 12288);
    __nv_bfloat16* Bh = (__nv_bfloat16*)(smem_raw + 24576);   // [2][16*136]
    __nv_bfloat16* Bl = (__nv_bfloat16*)(smem_raw + 33280);

    const int tid = threadIdx.x;
    const int wid = tid >> 5;
    const int lane = tid & 31;
    const int warp_row = wid >> 1;   // 0..3 -> 32 rows
    const int warp_col = wid & 1;    // 0..1 -> 64 cols
    const int bm = blockIdx.y * 128;
    const int bn = blockIdx.x * 128;

    const int a_row = tid >> 1;          // 0..127
    const int a_col = (tid & 1) * 8;     // 0 or 8
    const int b_row = tid >> 4;          // 0..15
    const int b_col = (tid & 15) * 8;    // 0..120

    const float* Aptr = A + (size_t)(bm + a_row) * K + a_col;
    const float* Bptr = Bw + (size_t)b_row * N + bn + b_col;

    wmma::fragment<wmma::accumulator, 16, 16, 16, float> acc[2][4];
#pragma unroll
    for (int mm = 0; mm < 2; mm++)
#pragma unroll
        for (int nn = 0; nn < 4; nn++) wmma::fill_fragment(acc[mm][nn], 0.0f);

    float4 ra0, ra1, rb0, rb1;
    ra0 = *(const float4*)(Aptr);
    ra1 = *(const float4*)(Aptr + 4);
    rb0 = *(const float4*)(Bptr);
    rb1 = *(const float4*)(Bptr + 4);
    sts8(&Ah[a_row * 24 + a_col], &Al[a_row * 24 + a_col], ra0, ra1);
    sts8(&Bh[b_row * 136 + b_col], &Bl[b_row * 136 + b_col], rb0, rb1);
    __syncthreads();

    const int NK = K >> 4;
    int cur = 0;
    for (int kt = 0; kt < NK; kt++) {
        const bool has_next = (kt + 1 < NK);
        if (has_next) {
            ra0 = *(const float4*)(Aptr + (kt + 1) * 16);
            ra1 = *(const float4*)(Aptr + (kt + 1) * 16 + 4);
            rb0 = *(const float4*)(Bptr + (size_t)(kt + 1) * 16 * N);
            rb1 = *(const float4*)(Bptr + (size_t)(kt + 1) * 16 * N + 4);
        }

        const __nv_bfloat16* Ahc = Ah + cur * 3072;
        const __nv_bfloat16* Alc = Al + cur * 3072;
        const __nv_bfloat16* Bhc = Bh + cur * 2176;
        const __nv_bfloat16* Blc = Bl + cur * 2176;

        wmma::fragment<wmma::matrix_a, 16, 16, 16, __nv_bfloat16, wmma::row_major> ah[2], al[2];
#pragma unroll
        for (int mm = 0; mm < 2; mm++) {
            wmma::load_matrix_sync(ah[mm], Ahc + (warp_row * 32 + mm * 16) * 24, 24);
            wmma::load_matrix_sync(al[mm], Alc + (warp_row * 32 + mm * 16) * 24, 24);
        }
#pragma unroll
        for (int nn = 0; nn < 4; nn++) {
            wmma::fragment<wmma::matrix_b, 16, 16, 16, __nv_bfloat16, wmma::row_major> bh, bl;
            wmma::load_matrix_sync(bh, Bhc + warp_col * 64 + nn * 16, 136);
            wmma::load_matrix_sync(bl, Blc + warp_col * 64 + nn * 16, 136);
#pragma unroll
            for (int mm = 0; mm < 2; mm++) {
                wmma::mma_sync(acc[mm][nn], ah[mm], bh, acc[mm][nn]);
                wmma::mma_sync(acc[mm][nn], ah[mm], bl, acc[mm][nn]);
                wmma::mma_sync(acc[mm][nn], al[mm], bh, acc[mm][nn]);
            }
        }

        if (has_next) {
            int nxt = cur ^ 1;
            sts8(&Ah[nxt * 3072 + a_row * 24 + a_col], &Al[nxt * 3072 + a_row * 24 + a_col], ra0, ra1);
            sts8(&Bh[nxt * 2176 + b_row * 136 + b_col], &Bl[nxt * 2176 + b_row * 136 + b_col], rb0, rb1);
        }
        __syncthreads();
        cur ^= 1;
    }

    // Epilogue: per-warp 32x36 fp32 patch in (now free) smem
    float* patch = (float*)smem_raw + wid * 1152;
    const int crow = bm + warp_row * 32;
#pragma unroll
    for (int h = 0; h < 2; h++) {
        wmma::store_matrix_sync(patch, acc[0][2 * h], 36, wmma::mem_row_major);
        wmma::store_matrix_sync(patch + 16, acc[0][2 * h + 1], 36, wmma::mem_row_major);
        wmma::store_matrix_sync(patch + 16 * 36, acc[1][2 * h], 36, wmma::mem_row_major);
        wmma::store_matrix_sync(patch + 16 * 36 + 16, acc[1][2 * h + 1], 36, wmma::mem_row_major);
        __syncwarp();
        const int ccol = bn + warp_col * 64 + h * 32;
        for (int i = lane; i < 1024; i += 32) {
            int r = i >> 5, c = i & 31;
            float val = patch[r * 36 + c] + bias[ccol + c];
            size_t idx = (size_t)(crow + r) * N + ccol + c;
            if (Chi) {
                __nv_bfloat16 hi, lo;
                split_bf16(val, hi, lo);
                Chi[idx] = hi;
                Clo[idx] = lo;
            } else {
                Cf[idx] = val;
            }
        }
        __syncwarp();
    }
}

// ---------------------------------------------------------------------------
// Flash attention (causal). One block = one (b,h) x one 64-query tile.
// 256 thr / 8 warps. bf16 3-term split for QK^T and PV; fp32 online softmax.
// Scale 1/sqrt(D)=0.125 applied to S (exact).
// ---------------------------------------------------------------------------
__global__ __launch_bounds__(256) void attn_kernel()
{
    extern __shared__ __align__(16) char sm_raw[];
    __nv_bfloat16* Qh = (__nv_bfloat16*)(sm_raw);            // [64][72]
    __nv_bfloat16* Ql = (__nv_bfloat16*)(sm_raw + 9216);
    __nv_bfloat16* Kh = (__nv_bfloat16*)(sm_raw + 18432);    // K then V
    __nv_bfloat16* Kl = (__nv_bfloat16*)(sm_raw + 27648);
    __nv_bfloat16* Ph = (__nv_bfloat16*)(sm_raw + 36864);
    __nv_bfloat16* Pl = (__nv_bfloat16*)(sm_raw + 46080);
    float* Ss = (float*)(sm_raw + 55296);                    // [64][68]
    float* Os = (float*)(sm_raw + 72704);                    // [64][68]
    float* row_m = (float*)(sm_raw + 90112);                 // [64]
    float* row_l = (float*)(sm_raw + 90368);                 // [64]

    const int tid = threadIdx.x;
    const int wid = tid >> 5;
    const int lane = tid & 31;
    const int qblock = blockIdx.x;     // 0..31
    const int bh = blockIdx.y;         // 0..63
    const int b = bh >> 4, h = bh & 15;

    const int r = tid >> 2;            // 0..63
    const int c16 = (tid & 3) * 16;    // 16-col segment

    // Q tile (bf16 hi/lo straight from gmem)
    {
        size_t base = (size_t)(b * TT + qblock * 64 + r) * 3072 + h * 64 + c16;
        *(uint4*)&Qh[r * 72 + c16]     = *(const uint4*)(g_qkv_hi + base);
        *(uint4*)&Qh[r * 72 + c16 + 8] = *(const uint4*)(g_qkv_hi + base + 8);
        *(uint4*)&Ql[r * 72 + c16]     = *(const uint4*)(g_qkv_lo + base);
        *(uint4*)&Ql[r * 72 + c16 + 8] = *(const uint4*)(g_qkv_lo + base + 8);
    }
    for (int i = tid; i < 64 * 68; i += 256) Os[i] = 0.0f;
    if (tid < 64) { row_m[tid] = -1e30f; row_l[tid] = 0.0f; }
    __syncthreads();

    const int warp_m = wid >> 1;   // 0..3 -> 16 query rows
    const int warp_n = wid & 1;    // 0..1 -> 32 cols (2 frags)

    for (int j = 0; j <= qblock; j++) {
        // K tile
        {
            size_t base = (size_t)(b * TT + j * 64 + r) * 3072 + 1024 + h * 64 + c16;
            *(uint4*)&Kh[r * 72 + c16]     = *(const uint4*)(g_qkv_hi + base);
            *(uint4*)&Kh[r * 72 + c16 + 8] = *(const uint4*)(g_qkv_hi + base + 8);
            *(uint4*)&Kl[r * 72 + c16]     = *(const uint4*)(g_qkv_lo + base);
            *(uint4*)&Kl[r * 72 + c16 + 8] = *(const uint4*)(g_qkv_lo + base + 8);
        }
        __syncthreads();

        // S = Q @ K^T  (3-term bf16)
        {
            wmma::fragment<wmma::accumulator, 16, 16, 16, float> sa[2];
            wmma::fill_fragment(sa[0], 0.0f);
            wmma::fill_fragment(sa[1], 0.0f);
#pragma unroll
            for (int kk = 0; kk < 64; kk += 16) {
                wmma::fragment<wmma::matrix_a, 16, 16, 16, __nv_bfloat16, wmma::row_major> ah, al;
                wmma::load_matrix_sync(ah, Qh + (warp_m * 16) * 72 + kk, 72);
                wmma::load_matrix_sync(al, Ql + (warp_m * 16) * 72 + kk, 72);
#pragma unroll
                for (int nn = 0; nn < 2; nn++) {
                    wmma::fragment<wmma::matrix_b, 16, 16, 16, __nv_bfloat16, wmma::col_major> bh2, bl2;
                    wmma::load_matrix_sync(bh2, Kh + (warp_n * 32 + nn * 16) * 72 + kk, 72);
                    wmma::load_matrix_sync(bl2, Kl + (warp_n * 32 + nn * 16) * 72 + kk, 72);
                    wmma::mma_sync(sa[nn], ah, bh2, sa[nn]);
                    wmma::mma_sync(sa[nn], ah, bl2, sa[nn]);
                    wmma::mma_sync(sa[nn], al, bh2, sa[nn]);
                }
            }
#pragma unroll
            for (int nn = 0; nn < 2; nn++)
                wmma::store_matrix_sync(Ss + (warp_m * 16) * 68 + warp_n * 32 + nn * 16,
                                        sa[nn], 68, wmma::mem_row_major);
        }
        __syncthreads();

        // V tile into Kh/Kl (K reads done)
        {
            size_t base = (size_t)(b * TT + j * 64 + r) * 3072 + 2048 + h * 64 + c16;
            *(uint4*)&Kh[r * 72 + c16]     = *(const uint4*)(g_qkv_hi + base);
            *(uint4*)&Kh[r * 72 + c16 + 8] = *(const uint4*)(g_qkv_hi + base + 8);
            *(uint4*)&Kl[r * 72 + c16]     = *(const uint4*)(g_qkv_lo + base);
            *(uint4*)&Kl[r * 72 + c16 + 8] = *(const uint4*)(g_qkv_lo + base + 8);
        }

        // Online softmax; warp wid owns rows wid*8..wid*8+7
        const bool diag = (j == qblock);
#pragma unroll
        for (int rr = 0; rr < 8; rr++) {
            int row = wid * 8 + rr;
            float s0 = Ss[row * 68 + lane] * 0.125f;
            float s1 = Ss[row * 68 + 32 + lane] * 0.125f;
            if (diag) {
                if (lane > row) s0 = -1e30f;
                if (32 + lane > row) s1 = -1e30f;
            }
            float mt = fmaxf(s0, s1);
#pragma unroll
            for (int off = 16; off; off >>= 1)
                mt = fmaxf(mt, __shfl_xor_sync(0xFFFFFFFFu, mt, off));
            float mo = row_m[row];
            float mn = fmaxf(mo, mt);
            float alpha = __expf(mo - mn);
            float p0 = __expf(s0 - mn);
            float p1 = __expf(s1 - mn);
            __nv_bfloat16 hi, lo;
            split_bf16(p0, hi, lo);
            Ph[row * 72 + lane] = hi; Pl[row * 72 + lane] = lo;
            split_bf16(p1, hi, lo);
            Ph[row * 72 + 32 + lane] = hi; Pl[row * 72 + 32 + lane] = lo;
            float psum = p0 + p1;
#pragma unroll
            for (int off = 16; off; off >>= 1)
                psum += __shfl_xor_sync(0xFFFFFFFFu, psum, off);
            if (lane == 0) {
                row_m[row] = mn;
                row_l[row] = alpha * row_l[row] + psum;
            }
            Os[row * 68 + lane] *= alpha;
            Os[row * 68 + 32 + lane] *= alpha;
        }
        __syncthreads();

        // O += P @ V  (3-term bf16)
        {
            wmma::fragment<wmma::accumulator, 16, 16, 16, float> oa[2];
#pragma unroll
            for (int nn = 0; nn < 2; nn++)
                wmma::load_matrix_sync(oa[nn],
                                       Os + (warp_m * 16) * 68 + warp_n * 32 + nn * 16,
                                       68, wmma::mem_row_major);
#pragma unroll
            for (int kk = 0; kk < 64; kk += 16) {
                wmma::fragment<wmma::matrix_a, 16, 16, 16, __nv_bfloat16, wmma::row_major> ph, pl;
                wmma::load_matrix_sync(ph, Ph + (warp_m * 16) * 72 + kk, 72);
                wmma::load_matrix_sync(pl, Pl + (warp_m * 16) * 72 + kk, 72);
#pragma unroll
                for (int nn = 0; nn < 2; nn++) {
                    wmma::fragment<wmma::matrix_b, 16, 16, 16, __nv_bfloat16, wmma::row_major> vh, vl;
                    wmma::load_matrix_sync(vh, Kh + kk * 72 + warp_n * 32 + nn * 16, 72);
                    wmma::load_matrix_sync(vl, Kl + kk * 72 + warp_n * 32 + nn * 16, 72);
                    wmma::mma_sync(oa[nn], ph, vh, oa[nn]);
                    wmma::mma_sync(oa[nn], ph, vl, oa[nn]);
                    wmma::mma_sync(oa[nn], pl, vh, oa[nn]);
                }
            }
#pragma unroll
            for (int nn = 0; nn < 2; nn++)
                wmma::store_matrix_sync(Os + (warp_m * 16) * 68 + warp_n * 32 + nn * 16,
                                        oa[nn], 68, wmma::mem_row_major);
        }
        __syncthreads();
    }

    // Normalize and write y[b, t, h*64 + d]
#pragma unroll
    for (int rr = 0; rr < 8; rr++) {
        int row = wid * 8 + rr;
        float inv = 1.0f / row_l[row];
        float* dst = g_y + (size_t)(b * TT + qblock * 64 + row) * 1024 + h * 64;
        dst[lane] = Os[row * 68 + lane] * inv;
        dst[32 + lane] = Os[row * 68 + 32 + lane] * inv;
    }
}

// ---------------------------------------------------------------------------
// kernel_launch
// Inputs: 0=x, 1=mask (ignored; causal known), 2=W_attn, 3=b_attn,
//         4=W_proj, 5=b_proj. Output fp32 [4,2048,1024].
// ---------------------------------------------------------------------------
extern "C" void kernel_launch(void* const* d_in, const int* in_sizes, int n_in,
                              void* d_out, int out_size)
{
    const float* x  = (const float*)d_in[0];
    const float* Wa = (const float*)d_in[2];
    const float* ba = (const float*)d_in[3];
    const float* Wp = (const float*)d_in[4];
    const float* bp = (const float*)d_in[5];
    float* out = (float*)d_out;

    void *qh_ptr = nullptr, *ql_ptr = nullptr, *y_ptr = nullptr;
    cudaGetSymbolAddress(&qh_ptr, g_qkv_hi);
    cudaGetSymbolAddress(&ql_ptr, g_qkv_lo);
    cudaGetSymbolAddress(&y_ptr, g_y);

    cudaFuncSetAttribute((const void*)attn_kernel,
                         cudaFuncAttributeMaxDynamicSharedMemorySize, 90624);

    // qkv = x @ W_attn + b_attn  -> bf16 hi/lo split output
    gemm_bf16_kernel<<<dim3(3072 / 128, 8192 / 128), 256>>>(
        x, Wa, ba, nullptr, (__nv_bfloat16*)qh_ptr, (__nv_bfloat16*)ql_ptr,
        8192, 3072, 1024);

    // y = causal MHA(qkv)
    attn_kernel<<<dim3(TT / 64, TB * TH), 256, 90624>>>();

    // out = y @ W_proj + b_proj  -> fp32 output
    gemm_bf16_kernel<<<dim3(1024 / 128, 8192 / 128), 256>>>(
        (const float*)y_ptr, Wp, bp, out, nullptr, nullptr,
        8192, 1024, 1024);
}